// round 1
// baseline (speedup 1.0000x reference)
#include <cuda_runtime.h>
#include <math_constants.h>

#define HH 96
#define WW 128
#define CC 21
#define NN (HH*WW)
#define RR 16
#define TAPS (2*RR+1)
#define NUM_ITER 5

// scratch (allocation-free rule: __device__ globals)
__device__ float g_q[NN*CC];     // [h][w][c]
__device__ float g_tmp[NN*CC];   // blur-x result, [h][w][c]
__device__ float g_wcomb[CC*CC]; // compat @ (sw+bw)

// ---------------------------------------------------------------------------
// Precompute Wcomb = compat @ (sw + bw)   (C x C, runs once)
// ---------------------------------------------------------------------------
__global__ void wcomb_kernel(const float* __restrict__ sw,
                             const float* __restrict__ bw,
                             const float* __restrict__ compat) {
    int i = threadIdx.x;
    if (i < CC*CC) {
        int r = i / CC, c = i % CC;
        float s = 0.f;
        #pragma unroll
        for (int k = 0; k < CC; k++)
            s += compat[r*CC + k] * (sw[k*CC + c] + bw[k*CC + c]);
        g_wcomb[i] = s;
    }
}

// ---------------------------------------------------------------------------
// Kernel A: per-row. softmax over classes, then Gaussian blur along x.
// grid = H rows, block = W threads (one per x).
// ---------------------------------------------------------------------------
__global__ __launch_bounds__(WW) void softmax_blurx(const float* __restrict__ qin,
                                                    int first_iter) {
    __shared__ float p[WW][CC];     // 10752 B, stride 21 (odd) -> conflict-free
    __shared__ float g[TAPS];

    const int h = blockIdx.x;
    const int x = threadIdx.x;

    if (x < TAPS) {
        float d = (float)(x - RR);
        g[x] = __expf(-d*d * (1.0f/18.0f));
    }

    const float* qp = (first_iter ? qin : (const float*)g_q) + (h*WW + x)*CC;

    // softmax over 21 classes
    float v[CC];
    float m = -CUDART_INF_F;
    #pragma unroll
    for (int c = 0; c < CC; c++) { v[c] = qp[c]; m = fmaxf(m, v[c]); }
    float s = 0.f;
    #pragma unroll
    for (int c = 0; c < CC; c++) { v[c] = __expf(v[c] - m); s += v[c]; }
    float inv = 1.0f / s;
    #pragma unroll
    for (int c = 0; c < CC; c++) p[x][c] = v[c] * inv;

    __syncthreads();

    // blur along x (truncated Gaussian, sigma=3, R=16)
    const int lo = max(0, x - RR);
    const int hi = min(WW - 1, x + RR);
    float acc[CC];
    #pragma unroll
    for (int c = 0; c < CC; c++) acc[c] = 0.f;
    for (int xx = lo; xx <= hi; xx++) {
        float w = g[xx - x + RR];
        #pragma unroll
        for (int c = 0; c < CC; c++) acc[c] += w * p[xx][c];
    }

    float* tp = g_tmp + (h*WW + x)*CC;
    #pragma unroll
    for (int c = 0; c < CC; c++) tp[c] = acc[c];
}

// ---------------------------------------------------------------------------
// Kernel B: per-column. Gaussian blur along y, normalize by separable row-sum,
// apply Wcomb matvec, q = u - pairwise. Last iteration writes d_out permuted
// to (1, W, H, C).
// grid = W columns, block = H threads (one per y).
// ---------------------------------------------------------------------------
__global__ __launch_bounds__(HH) void blury_update(const float* __restrict__ u,
                                                   float* __restrict__ out,
                                                   int last_iter) {
    __shared__ float col[HH][CC];   // 8064 B
    __shared__ float wc[CC*CC];
    __shared__ float g[TAPS];

    const int x = blockIdx.x;
    const int y = threadIdx.x;

    if (y < TAPS) {
        float d = (float)(y - RR);
        g[y] = __expf(-d*d * (1.0f/18.0f));
    }
    for (int i = y; i < CC*CC; i += HH) wc[i] = g_wcomb[i];

    const float* tp = g_tmp + (y*WW + x)*CC;
    #pragma unroll
    for (int c = 0; c < CC; c++) col[y][c] = tp[c];

    __syncthreads();

    // blur along y
    const int lo = max(0, y - RR);
    const int hi = min(HH - 1, y + RR);
    float s[CC];
    #pragma unroll
    for (int c = 0; c < CC; c++) s[c] = 0.f;
    for (int yy = lo; yy <= hi; yy++) {
        float w = g[yy - y + RR];
        #pragma unroll
        for (int c = 0; c < CC; c++) s[c] += w * col[yy][c];
    }

    // separable normalizer: norm(x,y) = Sx(x) * Sy(y) (truncated sums, exact
    // w.r.t. our truncated kernel; tail error ~1e-7 vs dense reference)
    float Sx = 0.f, Sy = 0.f;
    #pragma unroll
    for (int d = -RR; d <= RR; d++) {
        int xx = x + d;
        int yy = y + d;
        float w = g[d + RR];
        if (xx >= 0 && xx < WW) Sx += w;
        if (yy >= 0 && yy < HH) Sy += w;
    }
    float invn = 1.0f / (Sx * Sy);
    #pragma unroll
    for (int c = 0; c < CC; c++) s[c] *= invn;

    // pairwise = Wcomb @ spatial_out ;  q = u - pairwise
    const float* up = u + (y*WW + x)*CC;
    float qn[CC];
    #pragma unroll
    for (int cc = 0; cc < CC; cc++) {
        float a = 0.f;
        #pragma unroll
        for (int c = 0; c < CC; c++) a += wc[cc*CC + c] * s[c];
        qn[cc] = up[cc] - a;
    }

    if (last_iter) {
        // out[0][w][h][c]
        float* op = out + (x*HH + y)*CC;
        #pragma unroll
        for (int c = 0; c < CC; c++) op[c] = qn[c];
    } else {
        float* qp = g_q + (y*WW + x)*CC;
        #pragma unroll
        for (int c = 0; c < CC; c++) qp[c] = qn[c];
    }
}

// ---------------------------------------------------------------------------
extern "C" void kernel_launch(void* const* d_in, const int* in_sizes, int n_in,
                              void* d_out, int out_size) {
    const float* unaries = (const float*)d_in[0];   // (1,96,128,21)
    // d_in[1] = rgb — dead: bilateral filter output is unused in the source
    const float* sw      = (const float*)d_in[2];   // (21,21)
    const float* bw      = (const float*)d_in[3];   // (21,21)
    const float* compat  = (const float*)d_in[4];   // (21,21)
    float* out           = (float*)d_out;           // (1,128,96,21)

    wcomb_kernel<<<1, 512>>>(sw, bw, compat);

    for (int it = 0; it < NUM_ITER; it++) {
        softmax_blurx<<<HH, WW>>>(unaries, it == 0 ? 1 : 0);
        blury_update<<<WW, HH>>>(unaries, out, it == NUM_ITER - 1 ? 1 : 0);
    }
}